// round 1
// baseline (speedup 1.0000x reference)
#include <cuda_runtime.h>
#include <math.h>

#define B 128
#define T 2048
#define D 64
#define H 128
#define O 32

// Scratch (device globals — no allocation allowed in kernel_launch).
// g_s0 / g_s1 are ping-ponged: xp0 -> s0, h1 -> s1, xp1 -> s0, h2 -> s1.
__device__ float g_s0[(size_t)B * T * H];
__device__ float g_s1[(size_t)B * T * H];

// ---------------------------------------------------------------------------
// Input-projection GEMM: out[b,t,j] = sum_k in[b,t,k] * W[j,k] + b1[j] + b2[j]
// Only computed for t < lengths[b] (later rows are never consumed).
// One block = 128 threads, handles CT timesteps of one batch row.
// W row lives in registers (K regs/thread); x tile staged in shared,
// read back as broadcast float4.
// ---------------------------------------------------------------------------
template <int K>
__global__ __launch_bounds__(128) void proj_kernel(
    const float* __restrict__ in,   // [B,T,K]
    float* __restrict__ out,        // [B,T,H]
    const float* __restrict__ W,    // [H,K]
    const float* __restrict__ b1,
    const float* __restrict__ b2,
    const int* __restrict__ lengths)
{
    constexpr int CT = 16;
    const int b  = blockIdx.y;
    const int t0 = blockIdx.x * CT;
    const int len = lengths[b];
    if (t0 >= len) return;

    const int j = threadIdx.x;  // output index 0..127
    __shared__ float xs[CT][K];

    float w[K];
#pragma unroll
    for (int k = 0; k < K; k += 4) {
        float4 v = *(const float4*)(W + (size_t)j * K + k);
        w[k] = v.x; w[k + 1] = v.y; w[k + 2] = v.z; w[k + 3] = v.w;
    }
    const float bias = b1[j] + b2[j];

    const int nt = min(CT, len - t0);
    const float* inp = in + ((size_t)b * T + t0) * K;
    for (int idx = j; idx < nt * K; idx += 128)
        xs[idx / K][idx % K] = inp[idx];
    __syncthreads();

    for (int tt = 0; tt < nt; ++tt) {
        float a0 = bias, a1 = 0.f, a2 = 0.f, a3 = 0.f;
#pragma unroll
        for (int k = 0; k < K; k += 4) {
            float4 hv = *(const float4*)&xs[tt][k];
            a0 += hv.x * w[k];
            a1 += hv.y * w[k + 1];
            a2 += hv.z * w[k + 2];
            a3 += hv.w * w[k + 3];
        }
        out[((size_t)b * T + t0 + tt) * H + j] = (a0 + a1) + (a2 + a3);
    }
}

// ---------------------------------------------------------------------------
// Recurrence: for one batch row b (one CTA, 128 threads),
//   h = tanh(xp[b,t,:] + W_hh @ h),  t = 0..len[b]-1
// Thread j owns W_hh row j in 128 registers. h double-buffered in shared;
// reads are broadcast float4 LDS (conflict-free). One barrier per step.
// xp for step t+1 is prefetched during step t's dot product.
// ---------------------------------------------------------------------------
__global__ __launch_bounds__(128) void rec_kernel(
    const float* __restrict__ xp,   // [B,T,H]
    float* __restrict__ hout,       // [B,T,H]
    const float* __restrict__ W_hh, // [H,H]
    const int* __restrict__ lengths)
{
    const int b = blockIdx.x;
    const int j = threadIdx.x;
    const int len = lengths[b];

    __shared__ float h_sh[2][H];

    float w[H];
#pragma unroll
    for (int k = 0; k < H; k += 4) {
        float4 v = *(const float4*)(W_hh + (size_t)j * H + k);
        w[k] = v.x; w[k + 1] = v.y; w[k + 2] = v.z; w[k + 3] = v.w;
    }

    h_sh[0][j] = 0.0f;
    __syncthreads();

    const float* xrow = xp + (size_t)b * T * H + j;
    float* orow       = hout + (size_t)b * T * H + j;

    float xnext = (len > 0) ? xrow[0] : 0.0f;
    int cur = 0;

    for (int t = 0; t < len; ++t) {
        float a0 = xnext, a1 = 0.f, a2 = 0.f, a3 = 0.f;
        if (t + 1 < len) xnext = __ldg(xrow + (size_t)(t + 1) * H);

#pragma unroll
        for (int k = 0; k < H; k += 4) {
            float4 hv = *(const float4*)&h_sh[cur][k];
            a0 += hv.x * w[k];
            a1 += hv.y * w[k + 1];
            a2 += hv.z * w[k + 2];
            a3 += hv.w * w[k + 3];
        }
        float hn = tanhf((a0 + a1) + (a2 + a3));

        h_sh[cur ^ 1][j] = hn;
        orow[(size_t)t * H] = hn;
        cur ^= 1;
        __syncthreads();
    }
}

// ---------------------------------------------------------------------------
// FC: out[b,t,o] = (t < len[b]) ? h2[b,t,:]·W_fc[o,:] + b_fc[o] : b_fc[o]
// One warp per (b,t) row; lane = o. Lane o holds W_fc row o in 128 regs.
// h row loaded as float4 (lane l holds h[4l..4l+3]), broadcast via shfl.
// ---------------------------------------------------------------------------
__global__ __launch_bounds__(256) void fc_kernel(
    const float* __restrict__ h2,   // [B,T,H]
    float* __restrict__ out,        // [B,T,O]
    const float* __restrict__ Wfc,  // [O,H]
    const float* __restrict__ bfc,  // [O]
    const int* __restrict__ lengths)
{
    __shared__ int len_sh[B];
    const int tid  = threadIdx.x;
    const int lane = tid & 31;
    const int wid  = tid >> 5;
    if (tid < B) len_sh[tid] = lengths[tid];
    __syncthreads();

    float w[H];
#pragma unroll
    for (int k = 0; k < H; k += 4) {
        float4 v = *(const float4*)(Wfc + (size_t)lane * H + k);
        w[k] = v.x; w[k + 1] = v.y; w[k + 2] = v.z; w[k + 3] = v.w;
    }
    const float bias = bfc[lane];

    const int warps_per_blk = blockDim.x >> 5;
    const int nwarps = gridDim.x * warps_per_blk;
    const int gw = blockIdx.x * warps_per_blk + wid;

    for (int row = gw; row < B * T; row += nwarps) {
        const int b = row >> 11;       // T = 2048
        const int t = row & (T - 1);
        float acc = bias;
        if (t < len_sh[b]) {
            float4 hv = ((const float4*)(h2 + (size_t)row * H))[lane];
#pragma unroll
            for (int kk = 0; kk < 32; ++kk) {
                float x0 = __shfl_sync(0xffffffffu, hv.x, kk);
                float x1 = __shfl_sync(0xffffffffu, hv.y, kk);
                float x2 = __shfl_sync(0xffffffffu, hv.z, kk);
                float x3 = __shfl_sync(0xffffffffu, hv.w, kk);
                acc += x0 * w[4 * kk]     + x1 * w[4 * kk + 1]
                     + x2 * w[4 * kk + 2] + x3 * w[4 * kk + 3];
            }
        }
        out[(size_t)row * O + lane] = acc;
    }
}

// ---------------------------------------------------------------------------
extern "C" void kernel_launch(void* const* d_in, const int* in_sizes, int n_in,
                              void* d_out, int out_size)
{
    const float* x      = (const float*)d_in[0];
    const int*   lens   = (const int*)  d_in[1];
    const float* W_ih0  = (const float*)d_in[2];
    const float* W_hh0  = (const float*)d_in[3];
    const float* b_ih0  = (const float*)d_in[4];
    const float* b_hh0  = (const float*)d_in[5];
    const float* W_ih1  = (const float*)d_in[6];
    const float* W_hh1  = (const float*)d_in[7];
    const float* b_ih1  = (const float*)d_in[8];
    const float* b_hh1  = (const float*)d_in[9];
    const float* W_fc   = (const float*)d_in[10];
    const float* b_fc   = (const float*)d_in[11];
    float* out = (float*)d_out;

    float* s0;
    float* s1;
    cudaGetSymbolAddress((void**)&s0, g_s0);
    cudaGetSymbolAddress((void**)&s1, g_s1);

    dim3 pgrid(T / 16, B);

    // 1) xp0 = x @ W_ih0^T + b_ih0 + b_hh0   -> s0
    proj_kernel<D><<<pgrid, 128>>>(x, s0, W_ih0, b_ih0, b_hh0, lens);
    // 2) layer-0 recurrence                  -> h1 in s1
    rec_kernel<<<B, 128>>>(s0, s1, W_hh0, lens);
    // 3) xp1 = h1 @ W_ih1^T + b_ih1 + b_hh1  -> s0
    proj_kernel<H><<<pgrid, 128>>>(s1, s0, W_ih1, b_ih1, b_hh1, lens);
    // 4) layer-1 recurrence                  -> h2 in s1
    rec_kernel<<<B, 128>>>(s0, s1, W_hh1, lens);
    // 5) FC + zero-padding semantics         -> out
    fc_kernel<<<296, 256>>>(s1, out, W_fc, b_fc, lens);
}

// round 2
// speedup vs baseline: 1.1742x; 1.1742x over previous
#include <cuda_runtime.h>
#include <math.h>

#define B 128
#define T 2048
#define D 64
#define H 128
#define O 32
#define TILE 16

// Scratch (device globals). Ping-pong: xp0 -> s0, h1 -> s1, xp1 -> s0, h2 -> s1.
__device__ float g_s0[(size_t)B * T * H];
__device__ float g_s1[(size_t)B * T * H];

// ---------------------------------------------------------------------------
// helpers: packed f32x2 FMA (Blackwell FFMA2) + fast tanh (MUFU.TANH)
// ---------------------------------------------------------------------------
__device__ __forceinline__ unsigned long long ffma2(unsigned long long a,
                                                    unsigned long long b,
                                                    unsigned long long c) {
    unsigned long long d;
    asm("fma.rn.f32x2 %0, %1, %2, %3;" : "=l"(d) : "l"(a), "l"(b), "l"(c));
    return d;
}
__device__ __forceinline__ float f2lo(unsigned long long v) {
    return __uint_as_float((unsigned)(v & 0xffffffffull));
}
__device__ __forceinline__ float f2hi(unsigned long long v) {
    return __uint_as_float((unsigned)(v >> 32));
}
__device__ __forceinline__ float tanh_fast(float x) {
    float y;
    asm("tanh.approx.f32 %0, %1;" : "=f"(y) : "f"(x));
    return y;
}

// ---------------------------------------------------------------------------
// Input-projection GEMM: out[b,t,j] = in[b,t,:]·W[j,:] + b1[j] + b2[j]
// Computed only for t < lengths[b]. Thread j keeps W row packed as f32x2
// in registers; x tile staged in shared, consumed as 16B broadcast loads.
// ---------------------------------------------------------------------------
template <int K>
__global__ __launch_bounds__(128) void proj_kernel(
    const float* __restrict__ in,   // [B,T,K]
    float* __restrict__ out,        // [B,T,H]
    const float* __restrict__ W,    // [H,K]
    const float* __restrict__ b1,
    const float* __restrict__ b2,
    const int* __restrict__ lengths)
{
    constexpr int CT = 16;
    const int b  = blockIdx.y;
    const int t0 = blockIdx.x * CT;
    const int len = lengths[b];
    if (t0 >= len) return;

    const int j = threadIdx.x;
    __shared__ __align__(16) float xs[CT][K];

    unsigned long long wq[K / 2];
    {
        const ulonglong2* Wp = (const ulonglong2*)(W + (size_t)j * K);
#pragma unroll
        for (int i = 0; i < K / 4; ++i) {
            ulonglong2 v = Wp[i];
            wq[2 * i] = v.x; wq[2 * i + 1] = v.y;
        }
    }
    const float bias = b1[j] + b2[j];

    const int nt = min(CT, len - t0);
    const float* inp = in + ((size_t)b * T + t0) * K;
    for (int idx = j; idx < nt * K / 4; idx += 128)
        ((float4*)xs)[idx] = ((const float4*)inp)[idx];
    __syncthreads();

    for (int tt = 0; tt < nt; ++tt) {
        unsigned long long acc0 = 0ull, acc1 = 0ull;
        const ulonglong2* xr = (const ulonglong2*)&xs[tt][0];
#pragma unroll
        for (int i = 0; i < K / 4; ++i) {
            ulonglong2 hv = xr[i];
            acc0 = ffma2(wq[2 * i], hv.x, acc0);
            acc1 = ffma2(wq[2 * i + 1], hv.y, acc1);
        }
        float s = (f2lo(acc0) + f2hi(acc0)) + (f2lo(acc1) + f2hi(acc1));
        out[((size_t)b * T + t0 + tt) * H + j] = bias + s;
    }
}

// ---------------------------------------------------------------------------
// Recurrence: one CTA (512 threads, 16 warps) per batch row.
//   h = tanh(xp[b,t,:] + W_hh @ h)
// Output j is owned by 4 lanes of warp w=j/8 (lane = q*8 + j%8); lane q
// accumulates k in {4q+16i .. 4q+16i+3}, i=0..7 (interleaved quarters keep
// the broadcast LDS conflict-free). Partials reduced with 2 shfl.xor.
// xp is prefetched a full 16-step tile ahead (LDG -> regs -> STS).
// ---------------------------------------------------------------------------
__global__ __launch_bounds__(512) void rec_kernel(
    const float* __restrict__ xp,   // [B,T,H]
    float* __restrict__ hout,       // [B,T,H]
    const float* __restrict__ W_hh, // [H,H]
    const int* __restrict__ lengths)
{
    const int b    = blockIdx.x;
    const int tid  = threadIdx.x;
    const int lane = tid & 31;
    const int w    = tid >> 5;          // warp 0..15
    const int q    = lane >> 3;         // k-quarter 0..3
    const int jj   = lane & 7;
    const int j    = w * 8 + jj;        // output index 0..127
    const int len  = lengths[b];

    __shared__ float h_sh[2][H];
    __shared__ __align__(16) float xs[2][TILE * H];

    // weights: thread (j,q) holds w[j][4q + 16i + 0..3], i = 0..7, packed
    unsigned long long wq[16];
    {
        const float* wr = W_hh + (size_t)j * H + 4 * q;
#pragma unroll
        for (int i = 0; i < 8; ++i) {
            ulonglong2 v = *(const ulonglong2*)(wr + 16 * i);
            wq[2 * i] = v.x; wq[2 * i + 1] = v.y;
        }
    }

    const float* xbase = xp + (size_t)b * T * H;
    float* obase       = hout + (size_t)b * T * H;

    if (tid < H) h_sh[0][tid] = 0.0f;

    // tile pipeline: xs[0] = tile 0; r = tile 1 (in flight)
    float4 r;
    {
        float4 r0 = *(const float4*)(xbase + (size_t)w * H + lane * 4);
        *(float4*)&xs[0][w * H + lane * 4] = r0;
        int t2 = TILE + w;
        r = make_float4(0.f, 0.f, 0.f, 0.f);
        if (t2 < T) r = *(const float4*)(xbase + (size_t)t2 * H + lane * 4);
    }
    __syncthreads();

    int cur = 0, xbuf = 0;
    for (int t = 0; t < len; ++t) {
        const int tt = t & (TILE - 1);

        unsigned long long acc0 = 0ull, acc1 = 0ull;
        const float* hb = h_sh[cur] + 4 * q;
#pragma unroll
        for (int i = 0; i < 8; ++i) {
            ulonglong2 hv = *(const ulonglong2*)(hb + 16 * i);
            acc0 = ffma2(wq[2 * i], hv.x, acc0);
            acc1 = ffma2(wq[2 * i + 1], hv.y, acc1);
        }
        float s = (f2lo(acc0) + f2hi(acc0)) + (f2lo(acc1) + f2hi(acc1));
        s += __shfl_xor_sync(0xffffffffu, s, 8);
        s += __shfl_xor_sync(0xffffffffu, s, 16);

        if (q == 0) {
            float hn = tanh_fast(xs[xbuf][tt * H + j] + s);
            h_sh[cur ^ 1][j] = hn;
            obase[(size_t)t * H + j] = hn;
        }

        if (tt == TILE - 1) {
            __syncthreads();                       // step barrier + xs[xbuf^1] free
            *(float4*)&xs[xbuf ^ 1][w * H + lane * 4] = r;   // commit next tile
            int tn = t + 1 + TILE + w;             // kick tile after next
            if (tn < T) r = *(const float4*)(xbase + (size_t)tn * H + lane * 4);
            xbuf ^= 1;
            __syncthreads();                       // STS visibility
        } else {
            __syncthreads();                       // step barrier
        }
        cur ^= 1;
    }
}

// ---------------------------------------------------------------------------
// FC: out[b,t,o] = (t < len[b]) ? h2[b,t,:]·W_fc[o,:] + b_fc[o] : b_fc[o]
// One warp per (b,t) row; lane = o holds W_fc row o in registers.
// ---------------------------------------------------------------------------
__global__ __launch_bounds__(256) void fc_kernel(
    const float* __restrict__ h2,   // [B,T,H]
    float* __restrict__ out,        // [B,T,O]
    const float* __restrict__ Wfc,  // [O,H]
    const float* __restrict__ bfc,  // [O]
    const int* __restrict__ lengths)
{
    __shared__ int len_sh[B];
    const int tid  = threadIdx.x;
    const int lane = tid & 31;
    const int wid  = tid >> 5;
    if (tid < B) len_sh[tid] = lengths[tid];
    __syncthreads();

    float w[H];
#pragma unroll
    for (int k = 0; k < H; k += 4) {
        float4 v = *(const float4*)(Wfc + (size_t)lane * H + k);
        w[k] = v.x; w[k + 1] = v.y; w[k + 2] = v.z; w[k + 3] = v.w;
    }
    const float bias = bfc[lane];

    const int warps_per_blk = blockDim.x >> 5;
    const int nwarps = gridDim.x * warps_per_blk;
    const int gw = blockIdx.x * warps_per_blk + wid;

    for (int row = gw; row < B * T; row += nwarps) {
        const int b = row >> 11;       // T = 2048
        const int t = row & (T - 1);
        float acc = bias;
        if (t < len_sh[b]) {
            float4 hv = ((const float4*)(h2 + (size_t)row * H))[lane];
#pragma unroll
            for (int kk = 0; kk < 32; ++kk) {
                float x0 = __shfl_sync(0xffffffffu, hv.x, kk);
                float x1 = __shfl_sync(0xffffffffu, hv.y, kk);
                float x2 = __shfl_sync(0xffffffffu, hv.z, kk);
                float x3 = __shfl_sync(0xffffffffu, hv.w, kk);
                acc += x0 * w[4 * kk]     + x1 * w[4 * kk + 1]
                     + x2 * w[4 * kk + 2] + x3 * w[4 * kk + 3];
            }
        }
        out[(size_t)row * O + lane] = acc;
    }
}

// ---------------------------------------------------------------------------
extern "C" void kernel_launch(void* const* d_in, const int* in_sizes, int n_in,
                              void* d_out, int out_size)
{
    const float* x      = (const float*)d_in[0];
    const int*   lens   = (const int*)  d_in[1];
    const float* W_ih0  = (const float*)d_in[2];
    const float* W_hh0  = (const float*)d_in[3];
    const float* b_ih0  = (const float*)d_in[4];
    const float* b_hh0  = (const float*)d_in[5];
    const float* W_ih1  = (const float*)d_in[6];
    const float* W_hh1  = (const float*)d_in[7];
    const float* b_ih1  = (const float*)d_in[8];
    const float* b_hh1  = (const float*)d_in[9];
    const float* W_fc   = (const float*)d_in[10];
    const float* b_fc   = (const float*)d_in[11];
    float* out = (float*)d_out;

    float* s0;
    float* s1;
    cudaGetSymbolAddress((void**)&s0, g_s0);
    cudaGetSymbolAddress((void**)&s1, g_s1);

    dim3 pgrid(T / 16, B);

    proj_kernel<D><<<pgrid, 128>>>(x, s0, W_ih0, b_ih0, b_hh0, lens);
    rec_kernel<<<B, 512>>>(s0, s1, W_hh0, lens);
    proj_kernel<H><<<pgrid, 128>>>(s1, s0, W_ih1, b_ih1, b_hh1, lens);
    rec_kernel<<<B, 512>>>(s0, s1, W_hh1, lens);
    fc_kernel<<<296, 256>>>(s1, out, W_fc, b_fc, lens);
}